// round 14
// baseline (speedup 1.0000x reference)
#include <cuda_runtime.h>
#include <cuda_fp16.h>
#include <cstdint>

// ---------------------------------------------------------------------------
// SharedGroupGRU: B=16384 rows, IN=HID=128, KEY=64, RULES=16.
//   att == y_hard (argmax of logits+gumbel); logits[b,r] = q[b].hnext[b,r],
//   q = H @ (w_read @ W_write).
// Round 14: TM=128 A-resident rule loop. r13 (A resident, TM=64) cut fill
// bytes 53% and won -80us; weights re-streaming (805MB of 872MB fill) still
// dominates. TM=128 halves it again: fill 872 -> 470MB. A region 128KB ->
// 152KB smem, 1 CTA/SM x 512 thr (16 warps = 8 row-groups x 2 col-groups);
// 64-iteration pipeline self-overlaps so the old 1-CTA phase penalty should
// not return. fp16 2-limb math + argmax fix-up as validated r9-r13.
// ---------------------------------------------------------------------------

#define BTOT   16384
#define KDIM   128
#define RULES  16
#define TM     128
#define NA     (BTOT * KDIM)          // 2,097,152
#define NW     (RULES * 384 * KDIM)   // 786,432
#define WS     (RULES * 128 * KDIM)   // per-W-slab elems
#define TAU_FIX 2e-3f

typedef unsigned long long u64;

// -------------------- device scratch (static; no runtime alloc) ------------
__device__ float g_M[KDIM * KDIM];
__device__ float g_q[BTOT * KDIM];
__device__ float g_logits8[BTOT * RULES * 8];   // 8 fixed-order partials
__device__ int   g_fixmask[BTOT];
__device__ float g_hnext[(size_t)BTOT * RULES * KDIM];

// A slabs: 0=X16 1=Xl16 2=H16 3=Hl16, each [BTOT][128] fp16
__device__ __half g_Asp[4 * NA];
// W slabs: arr = s*3 + g (s:0=ih,1=hh; g:r,z,n), each [RULES][128][128] fp16
__device__ __half g_Wsp[6 * WS];

// -------------------- helpers ----------------------------------------------
__device__ __forceinline__ uint32_t smem_u32(const void* p) {
    uint32_t a;
    asm("{ .reg .u64 t; cvta.to.shared.u64 t, %1; cvt.u32.u64 %0, t; }" : "=r"(a) : "l"(p));
    return a;
}
__device__ __forceinline__ void cpasync16(uint32_t dst, const void* src) {
    asm volatile("cp.async.cg.shared.global [%0], [%1], 16;" :: "r"(dst), "l"(src));
}
__device__ __forceinline__ void ldsm4(uint32_t* r, uint32_t a) {
    asm volatile("ldmatrix.sync.aligned.m8n8.x4.shared.b16 {%0,%1,%2,%3}, [%4];"
                 : "=r"(r[0]), "=r"(r[1]), "=r"(r[2]), "=r"(r[3]) : "r"(a));
}
__device__ __forceinline__ void mma16816(float* d, const uint32_t* a, const uint32_t* b) {
    asm volatile("mma.sync.aligned.m16n8k16.row.col.f32.f16.f16.f32 "
                 "{%0,%1,%2,%3}, {%4,%5,%6,%7}, {%8,%9}, {%0,%1,%2,%3};"
                 : "+f"(d[0]), "+f"(d[1]), "+f"(d[2]), "+f"(d[3])
                 : "r"(a[0]), "r"(a[1]), "r"(a[2]), "r"(a[3]), "r"(b[0]), "r"(b[1]));
}
__device__ __forceinline__ float sigf(float x) {
    return __fdividef(1.0f, 1.0f + __expf(-x));
}
__device__ __forceinline__ float tanhf_fast(float x) {
    float e = __expf(2.0f * x);
    return 1.0f - __fdividef(2.0f, e + 1.0f);
}

// -------------------- smem geometry ----------------------------------------
// A resident: [chunk 0..3][tile 0..3], tile = 128 rows x 32 k (64B rows) = 8KB
#define A_TILE      8192
#define A_CHUNK     32768              // 4 tiles
#define B_BASE      131072             // after A region (128KB)
#define B_ARR       2048               // 32 rows x 32 k fp16
#define B_STAGE     12288              // 6 arrs
#define SMEM_TOTAL  (B_BASE + 2 * B_STAGE)   // 155,648 B -> 1 CTA/SM

// ---------------------------------------------------------------------------
// kPre: fp16 conversions + M (last block).  [r9-validated]
// ---------------------------------------------------------------------------
__global__ void kPre(const float* __restrict__ X, const float* __restrict__ H,
                     const float* __restrict__ Wih, const float* __restrict__ Whh,
                     const float* __restrict__ wread, const float* __restrict__ wwrite) {
    if (blockIdx.x == gridDim.x - 1) {
        for (int o = threadIdx.x; o < KDIM * KDIM; o += blockDim.x) {
            int hp = o >> 7, h = o & 127;
            float s = 0.0f;
            #pragma unroll 8
            for (int k = 0; k < 64; ++k)
                s = fmaf(wread[hp * 64 + k], wwrite[k * 128 + h], s);
            g_M[o] = s;
        }
        return;
    }
    int i = blockIdx.x * blockDim.x + threadIdx.x;
    if (i < NA) {
        float v = X[i];
        __half h = __float2half_rn(v);
        g_Asp[i] = h;
        g_Asp[NA + i] = __float2half_rn(v - __half2float(h));
        v = H[i];
        h = __float2half_rn(v);
        g_Asp[2 * NA + i] = h;
        g_Asp[3 * NA + i] = __float2half_rn(v - __half2float(h));
    }
    if (i < NW) {
        int rule = i / 49152;
        int rem  = i - rule * 49152;
        int row384 = rem >> 7, k = rem & 127;
        int g = row384 >> 7, rowg = row384 & 127;
        size_t dst = ((size_t)rule * 128 + rowg) * 128 + k;
        g_Wsp[(size_t)g * WS + dst]       = __float2half_rn(Wih[i]);
        g_Wsp[(size_t)(3 + g) * WS + dst] = __float2half_rn(Whh[i]);
    }
}

// ---------------------------------------------------------------------------
// kQ: g_q = H @ g_M (fp32; feeds argmax path)
// ---------------------------------------------------------------------------
__global__ void kQ(const float* __restrict__ Hin) {
    __shared__ float Hs[16][KDIM];
    int b0 = blockIdx.x * 16;
    for (int i = threadIdx.x; i < 16 * KDIM; i += blockDim.x)
        Hs[i >> 7][i & 127] = Hin[b0 * KDIM + i];
    __syncthreads();

    int h  = threadIdx.x & 127;
    int rr = threadIdx.x >> 7;
    float acc[8];
    #pragma unroll
    for (int j = 0; j < 8; ++j) acc[j] = 0.0f;
    for (int k = 0; k < KDIM; ++k) {
        float m = g_M[k * KDIM + h];
        #pragma unroll
        for (int j = 0; j < 8; ++j)
            acc[j] = fmaf(Hs[rr + 2 * j][k], m, acc[j]);
    }
    #pragma unroll
    for (int j = 0; j < 8; ++j)
        g_q[(size_t)(b0 + rr + 2 * j) * KDIM + h] = acc[j];
}

// ---------------------------------------------------------------------------
// kGRU loaders (512 threads)
// ---------------------------------------------------------------------------
__device__ __forceinline__ void load_A_all(uint32_t sb, int b0, int tid) {
    // 4 chunks x 4 tiles x 128 rows x 4 16B-chunks = 8192 ops (16/thread)
    #pragma unroll
    for (int it = 0; it < 16; ++it) {
        int idx  = it * 512 + tid;
        int ch   = idx >> 11;
        int tile = (idx >> 9) & 3;
        int row  = (idx >> 2) & 127;
        int cc   = idx & 3;
        uint32_t sw = (uint32_t)((cc ^ ((row >> 1) & 3)) << 4);
        const __half* src =
            g_Asp + (size_t)tile * NA + (size_t)(b0 + row) * KDIM + ch * 32 + cc * 8;
        cpasync16(sb + ch * A_CHUNK + tile * A_TILE + row * 64 + sw, src);
    }
}
__device__ __forceinline__ void load_B_stage(uint32_t bst, int rule, int n0c,
                                             int tid, int k0) {
    // 6 arrs x 32 rows x 4 16B-chunks = 768 ops
    #pragma unroll
    for (int it = 0; it < 2; ++it) {
        int idx = it * 512 + tid;
        if (idx < 768) {
            int arr = idx >> 7;
            int row = (idx >> 2) & 31;
            int cc  = idx & 3;
            uint32_t sw = (uint32_t)((cc ^ ((row >> 1) & 3)) << 4);
            const __half* src =
                g_Wsp + (size_t)arr * WS + ((size_t)rule * 128 + n0c + row) * KDIM + k0 + cc * 8;
            cpasync16(bst + arr * B_ARR + row * 64 + sw, src);
        }
    }
}

// ---------------------------------------------------------------------------
// kGRU: grid (128, 4), block 512 = 16 warps, 1 CTA/SM. Rule loop inside.
// Warp w: rg = w&7 (16-row group of 128 rows), cg = w>>3 (16-col group of 32).
// Each warp computes all 4 gate planes of its 16x16 tile (32 fp32 accums);
// in-register epilogue per rule; logits as 8 fixed-order partials.
// ---------------------------------------------------------------------------
__global__ void __launch_bounds__(512, 1)
kGRU(const float* __restrict__ Hin,
     const float* __restrict__ bih, const float* __restrict__ bhh) {
    extern __shared__ char smem[];
    const uint32_t sb = smem_u32(smem);
    const int tid = threadIdx.x;
    const int w = tid >> 5, lane = tid & 31;
    const int b0 = blockIdx.x * TM;
    const int n0c = blockIdx.y * 32;

    const int rg = w & 7;
    const int cg = w >> 3;

    const int rowa = rg * 16 + ((lane >> 3) & 1) * 8 + (lane & 7);
    const uint32_t aoff = (uint32_t)rowa * 64;
    const int swa = (rowa >> 1) & 3;
    const int hiA = lane >> 4;
    const int nbase = cg * 16 + ((lane >> 4) & 1) * 8 + (lane & 7);
    const uint32_t boff = (uint32_t)nbase * 64;
    const int swb = (nbase >> 1) & 3;
    const int hiB = (lane >> 3) & 1;

    float aR[2][4], aZ[2][4], aIN[2][4], aHN[2][4];
    #pragma unroll
    for (int nt = 0; nt < 2; ++nt)
        #pragma unroll
        for (int j = 0; j < 4; ++j)
            { aR[nt][j] = 0.f; aZ[nt][j] = 0.f; aIN[nt][j] = 0.f; aHN[nt][j] = 0.f; }

    // prologue: A (all) + B stage 0 in group 0; B stage 1 in group 1
    load_A_all(sb, b0, tid);
    load_B_stage(sb + B_BASE, 0, n0c, tid, 0);
    asm volatile("cp.async.commit_group;" ::: "memory");
    load_B_stage(sb + B_BASE + B_STAGE, 0, n0c, tid, 32);
    asm volatile("cp.async.commit_group;" ::: "memory");

    for (int ru = 0; ru < RULES; ++ru) {
        #pragma unroll
        for (int ch = 0; ch < 4; ++ch) {
            const int i = ru * 4 + ch;
            if (i < 63) asm volatile("cp.async.wait_group 1;" ::: "memory");
            else        asm volatile("cp.async.wait_group 0;" ::: "memory");
            __syncthreads();

            const uint32_t bst = sb + B_BASE + (uint32_t)(i & 1) * B_STAGE;
            #pragma unroll
            for (int ks = 0; ks < 2; ++ks) {
                const uint32_t kxa = (uint32_t)(((ks * 2 + hiA) ^ swa) << 4);
                const uint32_t kxb = (uint32_t)(((ks * 2 + hiB) ^ swb) << 4);
                #pragma unroll
                for (int s = 0; s < 2; ++s) {
                    uint32_t ah[4], al[4];
                    const uint32_t abase = sb + ch * A_CHUNK + (uint32_t)(s * 2) * A_TILE;
                    ldsm4(ah, abase + aoff + kxa);
                    ldsm4(al, abase + A_TILE + aoff + kxa);

                    uint32_t bb[4];
                    // r gate
                    ldsm4(bb, bst + (uint32_t)(s * 3 + 0) * B_ARR + boff + kxb);
                    mma16816(aR[0], ah, bb + 0); mma16816(aR[0], al, bb + 0);
                    mma16816(aR[1], ah, bb + 2); mma16816(aR[1], al, bb + 2);
                    // z gate
                    ldsm4(bb, bst + (uint32_t)(s * 3 + 1) * B_ARR + boff + kxb);
                    mma16816(aZ[0], ah, bb + 0); mma16816(aZ[0], al, bb + 0);
                    mma16816(aZ[1], ah, bb + 2); mma16816(aZ[1], al, bb + 2);
                    // n gate -> i_n (s=0) / h_n (s=1)
                    ldsm4(bb, bst + (uint32_t)(s * 3 + 2) * B_ARR + boff + kxb);
                    float (*aN)[4] = s ? aHN : aIN;
                    mma16816(aN[0], ah, bb + 0); mma16816(aN[0], al, bb + 0);
                    mma16816(aN[1], ah, bb + 2); mma16816(aN[1], al, bb + 2);
                }
            }
            __syncthreads();                       // stage consumed
            if (i < 62) {
                const int nx = i + 2;
                load_B_stage(sb + B_BASE + (uint32_t)(nx & 1) * B_STAGE,
                             nx >> 2, n0c, tid, (nx & 3) * 32);
                asm volatile("cp.async.commit_group;" ::: "memory");
            }
        }

        // ---- in-register epilogue for rule ru
        {
            float dR0 = 0.0f, dR1 = 0.0f;
            const size_t bgA = (size_t)(b0 + rg * 16 + (lane >> 2));
            #pragma unroll
            for (int nt = 0; nt < 2; ++nt) {
                const int colg = n0c + cg * 16 + nt * 8 + (lane & 3) * 2;
                float2 b_ir = *reinterpret_cast<const float2*>(&bih[ru * 384 + colg]);
                float2 b_iz = *reinterpret_cast<const float2*>(&bih[ru * 384 + 128 + colg]);
                float2 b_in = *reinterpret_cast<const float2*>(&bih[ru * 384 + 256 + colg]);
                float2 b_hr = *reinterpret_cast<const float2*>(&bhh[ru * 384 + colg]);
                float2 b_hz = *reinterpret_cast<const float2*>(&bhh[ru * 384 + 128 + colg]);
                float2 b_hn = *reinterpret_cast<const float2*>(&bhh[ru * 384 + 256 + colg]);
                #pragma unroll
                for (int rr2 = 0; rr2 < 2; ++rr2) {
                    const size_t bg = bgA + rr2 * 8;
                    float2 hp = *reinterpret_cast<const float2*>(&Hin[bg * KDIM + colg]);
                    float2 qv = *reinterpret_cast<const float2*>(&g_q[bg * KDIM + colg]);
                    const int j = rr2 * 2;
                    float ar0 = aR[nt][j]     + b_ir.x + b_hr.x;
                    float ar1 = aR[nt][j + 1] + b_ir.y + b_hr.y;
                    float az0 = aZ[nt][j]     + b_iz.x + b_hz.x;
                    float az1 = aZ[nt][j + 1] + b_iz.y + b_hz.y;
                    float n0 = tanhf_fast(fmaf(sigf(ar0), aHN[nt][j]     + b_hn.x,
                                               aIN[nt][j]     + b_in.x));
                    float n1 = tanhf_fast(fmaf(sigf(ar1), aHN[nt][j + 1] + b_hn.y,
                                               aIN[nt][j + 1] + b_in.y));
                    float o0 = fmaf(sigf(az0), hp.x - n0, n0);
                    float o1 = fmaf(sigf(az1), hp.y - n1, n1);
                    float2 o; o.x = o0; o.y = o1;
                    *reinterpret_cast<float2*>(
                        &g_hnext[(bg * RULES + ru) * KDIM + colg]) = o;
                    float dd = qv.x * o0 + qv.y * o1;
                    if (rr2 == 0) dR0 += dd; else dR1 += dd;
                }
            }
            dR0 += __shfl_xor_sync(0xffffffffu, dR0, 1);
            dR0 += __shfl_xor_sync(0xffffffffu, dR0, 2);
            dR1 += __shfl_xor_sync(0xffffffffu, dR1, 1);
            dR1 += __shfl_xor_sync(0xffffffffu, dR1, 2);
            if ((lane & 3) == 0) {
                const int p = blockIdx.y * 2 + cg;
                g_logits8[(bgA * RULES + ru) * 8 + p] = dR0;
                g_logits8[((bgA + 8) * RULES + ru) * 8 + p] = dR1;
            }
            #pragma unroll
            for (int nt = 0; nt < 2; ++nt)
                #pragma unroll
                for (int j = 0; j < 4; ++j)
                    { aR[nt][j] = 0.f; aZ[nt][j] = 0.f; aIN[nt][j] = 0.f; aHN[nt][j] = 0.f; }
        }
    }
}

// ---------------------------------------------------------------------------
// kSelect: fast argmax + candidate mask. One warp per b.
// ---------------------------------------------------------------------------
__global__ void kSelect(const float* __restrict__ gumbel,
                        float* __restrict__ out_h, float* __restrict__ out_attn) {
    int gwarp = (blockIdx.x * blockDim.x + threadIdx.x) >> 5;
    int lane = threadIdx.x & 31;
    if (gwarp >= BTOT) return;
    const int b = gwarp;

    float sv = -__int_as_float(0x7f800000);
    if (lane < RULES) {
        const float* p = g_logits8 + (size_t)(b * RULES + lane) * 8;
        sv = (((p[0] + p[1]) + (p[2] + p[3])) + ((p[4] + p[5]) + (p[6] + p[7])))
           + gumbel[b * RULES + lane];
    }
    float bv = sv; int bi = lane;
    #pragma unroll
    for (int off = 16; off; off >>= 1) {
        float ov = __shfl_xor_sync(0xffffffffu, bv, off);
        int   oi = __shfl_xor_sync(0xffffffffu, bi, off);
        if (ov > bv || (ov == bv && oi < bi)) { bv = ov; bi = oi; }
    }
    int rbest = bi;

    unsigned cmask = __ballot_sync(0xffffffffu, lane < RULES && sv >= bv - TAU_FIX);
    if (lane == 0)
        g_fixmask[b] = (__popc(cmask) > 1) ? (int)cmask : 0;

    float4 hv = *reinterpret_cast<const float4*>(
        g_hnext + ((size_t)b * RULES + rbest) * KDIM + lane * 4);
    *reinterpret_cast<float4*>(out_h + (size_t)b * KDIM + lane * 4) = hv;
    if (out_attn && lane < RULES)
        out_attn[b * RULES + lane] = (lane == rbest) ? 1.0f : 0.0f;
}

// ---------------------------------------------------------------------------
// kFix: fp32 recompute of candidate logits for ambiguous rows. [r9-validated]
// ---------------------------------------------------------------------------
__global__ void __launch_bounds__(128, 8)
kFix(const float* __restrict__ X, const float* __restrict__ H,
     const float* __restrict__ Wih, const float* __restrict__ Whh,
     const float* __restrict__ bih, const float* __restrict__ bhh,
     const float* __restrict__ gumbel,
     float* __restrict__ out_h, float* __restrict__ out_attn) {
    const int b = blockIdx.x;
    const int mask = g_fixmask[b];
    if (mask == 0) return;

    __shared__ float xs[KDIM], hs[KDIM], qs[KDIM], red[4];
    __shared__ int s_best;
    const int t = threadIdx.x;
    xs[t] = X[(size_t)b * KDIM + t];
    hs[t] = H[(size_t)b * KDIM + t];
    qs[t] = g_q[(size_t)b * KDIM + t];
    __syncthreads();

    float bestv = -__int_as_float(0x7f800000);
    int bestr = 0;
    for (int r = 0; r < RULES; ++r) {
        if (!((mask >> r) & 1)) continue;
        const float* Wi = Wih + (size_t)r * 384 * KDIM;
        const float* Wh = Whh + (size_t)r * 384 * KDIM;
        float ir = bih[r * 384 + t],        hr = bhh[r * 384 + t];
        float iz = bih[r * 384 + 128 + t],  hz = bhh[r * 384 + 128 + t];
        float in_ = bih[r * 384 + 256 + t], hn = bhh[r * 384 + 256 + t];
        const float* wir = Wi + (size_t)t * KDIM;
        const float* wiz = Wi + (size_t)(128 + t) * KDIM;
        const float* win = Wi + (size_t)(256 + t) * KDIM;
        const float* whr = Wh + (size_t)t * KDIM;
        const float* whz = Wh + (size_t)(128 + t) * KDIM;
        const float* whn = Wh + (size_t)(256 + t) * KDIM;
        for (int k = 0; k < KDIM; ++k) {
            float xk = xs[k], hk = hs[k];
            ir = fmaf(xk, wir[k], ir);   hr = fmaf(hk, whr[k], hr);
            iz = fmaf(xk, wiz[k], iz);   hz = fmaf(hk, whz[k], hz);
            in_ = fmaf(xk, win[k], in_); hn = fmaf(hk, whn[k], hn);
        }
        float rg = sigf(ir + hr);
        float zg = sigf(iz + hz);
        float nn = tanhf_fast(fmaf(rg, hn, in_));
        float hv = fmaf(zg, hs[t] - nn, nn);
        float d = qs[t] * hv;
        #pragma unroll
        for (int off = 16; off; off >>= 1)
            d += __shfl_xor_sync(0xffffffffu, d, off);
        if ((t & 31) == 0) red[t >> 5] = d;
        __syncthreads();
        if (t == 0) {
            float logit = red[0] + red[1] + red[2] + red[3];
            float s = logit + gumbel[b * RULES + r];
            if (s > bestv) { bestv = s; bestr = r; }
        }
        __syncthreads();
    }
    if (t == 0) s_best = bestr;
    __syncthreads();
    const int rtrue = s_best;

    out_h[(size_t)b * KDIM + t] =
        g_hnext[((size_t)b * RULES + rtrue) * KDIM + t];
    if (out_attn && t < RULES)
        out_attn[b * RULES + t] = (t == rtrue) ? 1.0f : 0.0f;
}

// ---------------------------------------------------------------------------
extern "C" void kernel_launch(void* const* d_in, const int* in_sizes, int n_in,
                              void* d_out, int out_size) {
    const float* X      = (const float*)d_in[0];
    const float* H      = (const float*)d_in[1];
    const float* Wih    = (const float*)d_in[2];
    const float* Whh    = (const float*)d_in[3];
    const float* bih    = (const float*)d_in[4];
    const float* bhh    = (const float*)d_in[5];
    const float* wread  = (const float*)d_in[6];
    const float* wwrite = (const float*)d_in[7];
    const float* gum    = (const float*)d_in[8];
    float* out = (float*)d_out;

    cudaFuncSetAttribute(kGRU, cudaFuncAttributeMaxDynamicSharedMemorySize, SMEM_TOTAL);

    kPre<<<NA / 256 + 1, 256>>>(X, H, Wih, Whh, wread, wwrite);
    kQ<<<BTOT / 16, 256>>>(H);

    dim3 grid(BTOT / TM, 4);
    kGRU<<<grid, 512, SMEM_TOTAL>>>(H, bih, bhh);

    const int HO = BTOT * KDIM;
    float* attn = (out_size >= HO + BTOT * RULES) ? out + HO : nullptr;
    kSelect<<<BTOT / 8, 256>>>(gum, out, attn);
    kFix<<<BTOT, 128>>>(X, H, Wih, Whh, bih, bhh, gum, out, attn);
}

// round 15
// speedup vs baseline: 1.1140x; 1.1140x over previous
#include <cuda_runtime.h>
#include <cuda_fp16.h>
#include <cstdint>

// ---------------------------------------------------------------------------
// SharedGroupGRU: B=16384 rows, IN=HID=128, KEY=64, RULES=16.
//   att == y_hard (argmax of logits+gumbel); logits[b,r] = q[b].hnext[b,r],
//   q = H @ (w_read @ W_write).
// Round 15: r13 config (A-resident rule loop, TM=64, 2 CTAs/SM — best at
// 733.5us) + 3-stage B pipeline (more latency slack per B group) + launch
// reorder so kGRU is the 4th launch (the slot ncu's -s5 -c1 capture lands
// on) to finally get kGRU stall data.
// fp16 2-limb math + argmax fix-up as validated r9-r14. TM=128 branch closed:
// r14 showed concurrency(2 CTAs) > fill-halving in value.
// ---------------------------------------------------------------------------

#define BTOT   16384
#define KDIM   128
#define RULES  16
#define TM     64
#define NA     (BTOT * KDIM)          // 2,097,152
#define NW     (RULES * 384 * KDIM)   // 786,432
#define WS     (RULES * 128 * KDIM)   // per-W-slab elems
#define TAU_FIX 2e-3f

typedef unsigned long long u64;

// -------------------- device scratch (static; no runtime alloc) ------------
__device__ float g_M[KDIM * KDIM];
__device__ float g_q[BTOT * KDIM];
__device__ float g_logits8[BTOT * RULES * 8];   // 8 fixed-order partials
__device__ int   g_fixmask[BTOT];
__device__ float g_hnext[(size_t)BTOT * RULES * KDIM];

// A slabs: 0=X16 1=Xl16 2=H16 3=Hl16, each [BTOT][128] fp16
__device__ __half g_Asp[4 * NA];
// W slabs: arr = s*3 + g (s:0=ih,1=hh; g:r,z,n), each [RULES][128][128] fp16
__device__ __half g_Wsp[6 * WS];

// -------------------- helpers ----------------------------------------------
__device__ __forceinline__ uint32_t smem_u32(const void* p) {
    uint32_t a;
    asm("{ .reg .u64 t; cvta.to.shared.u64 t, %1; cvt.u32.u64 %0, t; }" : "=r"(a) : "l"(p));
    return a;
}
__device__ __forceinline__ void cpasync16(uint32_t dst, const void* src) {
    asm volatile("cp.async.cg.shared.global [%0], [%1], 16;" :: "r"(dst), "l"(src));
}
__device__ __forceinline__ void ldsm4(uint32_t* r, uint32_t a) {
    asm volatile("ldmatrix.sync.aligned.m8n8.x4.shared.b16 {%0,%1,%2,%3}, [%4];"
                 : "=r"(r[0]), "=r"(r[1]), "=r"(r[2]), "=r"(r[3]) : "r"(a));
}
__device__ __forceinline__ void mma16816(float* d, const uint32_t* a, const uint32_t* b) {
    asm volatile("mma.sync.aligned.m16n8k16.row.col.f32.f16.f16.f32 "
                 "{%0,%1,%2,%3}, {%4,%5,%6,%7}, {%8,%9}, {%0,%1,%2,%3};"
                 : "+f"(d[0]), "+f"(d[1]), "+f"(d[2]), "+f"(d[3])
                 : "r"(a[0]), "r"(a[1]), "r"(a[2]), "r"(a[3]), "r"(b[0]), "r"(b[1]));
}
__device__ __forceinline__ float sigf(float x) {
    return __fdividef(1.0f, 1.0f + __expf(-x));
}
__device__ __forceinline__ float tanhf_fast(float x) {
    float e = __expf(2.0f * x);
    return 1.0f - __fdividef(2.0f, e + 1.0f);
}

// -------------------- smem geometry ----------------------------------------
// A resident: [chunk 0..3][tile 0..3] 4KB each (64 rows x 32 k, 64B rows)
#define A_TILE      4096
#define A_CHUNK     16384              // 4 tiles
#define B_BASE      65536              // after A region
#define B_ARR       2048               // 32 rows x 32 k fp16
#define B_STAGE     12288              // 6 arrs
#define NSTG        3
#define SMEM_TOTAL  (B_BASE + NSTG * B_STAGE)   // 102,400 B -> 2 CTAs/SM

// ---------------------------------------------------------------------------
// kPre: fp16 conversions + M (last block).  [r9-validated]
// ---------------------------------------------------------------------------
__global__ void kPre(const float* __restrict__ X, const float* __restrict__ H,
                     const float* __restrict__ Wih, const float* __restrict__ Whh,
                     const float* __restrict__ wread, const float* __restrict__ wwrite) {
    if (blockIdx.x == gridDim.x - 1) {
        for (int o = threadIdx.x; o < KDIM * KDIM; o += blockDim.x) {
            int hp = o >> 7, h = o & 127;
            float s = 0.0f;
            #pragma unroll 8
            for (int k = 0; k < 64; ++k)
                s = fmaf(wread[hp * 64 + k], wwrite[k * 128 + h], s);
            g_M[o] = s;
        }
        return;
    }
    int i = blockIdx.x * blockDim.x + threadIdx.x;
    if (i < NA) {
        float v = X[i];
        __half h = __float2half_rn(v);
        g_Asp[i] = h;
        g_Asp[NA + i] = __float2half_rn(v - __half2float(h));
        v = H[i];
        h = __float2half_rn(v);
        g_Asp[2 * NA + i] = h;
        g_Asp[3 * NA + i] = __float2half_rn(v - __half2float(h));
    }
    if (i < NW) {
        int rule = i / 49152;
        int rem  = i - rule * 49152;
        int row384 = rem >> 7, k = rem & 127;
        int g = row384 >> 7, rowg = row384 & 127;
        size_t dst = ((size_t)rule * 128 + rowg) * 128 + k;
        g_Wsp[(size_t)g * WS + dst]       = __float2half_rn(Wih[i]);
        g_Wsp[(size_t)(3 + g) * WS + dst] = __float2half_rn(Whh[i]);
    }
}

// ---------------------------------------------------------------------------
// kQ: g_q = H @ g_M (fp32; feeds argmax path)
// ---------------------------------------------------------------------------
__global__ void kQ(const float* __restrict__ Hin) {
    __shared__ float Hs[16][KDIM];
    int b0 = blockIdx.x * 16;
    for (int i = threadIdx.x; i < 16 * KDIM; i += blockDim.x)
        Hs[i >> 7][i & 127] = Hin[b0 * KDIM + i];
    __syncthreads();

    int h  = threadIdx.x & 127;
    int rr = threadIdx.x >> 7;
    float acc[8];
    #pragma unroll
    for (int j = 0; j < 8; ++j) acc[j] = 0.0f;
    for (int k = 0; k < KDIM; ++k) {
        float m = g_M[k * KDIM + h];
        #pragma unroll
        for (int j = 0; j < 8; ++j)
            acc[j] = fmaf(Hs[rr + 2 * j][k], m, acc[j]);
    }
    #pragma unroll
    for (int j = 0; j < 8; ++j)
        g_q[(size_t)(b0 + rr + 2 * j) * KDIM + h] = acc[j];
}

// ---------------------------------------------------------------------------
// kZero: clear fixmask (also positions kGRU as 4th launch for ncu capture)
// ---------------------------------------------------------------------------
__global__ void kZero() {
    int i = blockIdx.x * blockDim.x + threadIdx.x;
    if (i < BTOT) g_fixmask[i] = 0;
}

// ---------------------------------------------------------------------------
// kGRU loaders (256 threads)
// ---------------------------------------------------------------------------
__device__ __forceinline__ void load_A_all(uint32_t sb, int b0, int tid) {
    // 4 chunks x 4 tiles x 64 rows x 4 16B-chunks = 4096 ops (16/thread)
    #pragma unroll
    for (int it = 0; it < 16; ++it) {
        int idx  = it * 256 + tid;
        int ch   = idx >> 10;
        int tile = (idx >> 8) & 3;
        int row  = (idx >> 2) & 63;
        int cc   = idx & 3;
        uint32_t sw = (uint32_t)((cc ^ ((row >> 1) & 3)) << 4);
        const __half* src =
            g_Asp + (size_t)tile * NA + (size_t)(b0 + row) * KDIM + ch * 32 + cc * 8;
        cpasync16(sb + ch * A_CHUNK + tile * A_TILE + row * 64 + sw, src);
    }
}
__device__ __forceinline__ void load_B_stage(uint32_t bst, int rule, int n0c,
                                             int tid, int k0) {
    // 6 arrs x 32 rows x 4 16B-chunks = 768 ops (3/thread)
    #pragma unroll
    for (int a = 0; a < 3; ++a) {
        int idx = a * 256 + tid;
        int arr = idx >> 7;
        int row = (idx >> 2) & 31;
        int cc  = idx & 3;
        uint32_t sw = (uint32_t)((cc ^ ((row >> 1) & 3)) << 4);
        const __half* src =
            g_Wsp + (size_t)arr * WS + ((size_t)rule * 128 + n0c + row) * KDIM + k0 + cc * 8;
        cpasync16(bst + arr * B_ARR + row * 64 + sw, src);
    }
}

// ---------------------------------------------------------------------------
// kGRU: grid (256, 4), block 256 = 8 warps, 2 CTAs/SM. Rule loop, 3-stage B.
// Warp w: rg = w&3 (16-row group), cg = w>>2 (16-col group of CTA's 32 cols).
// Warp computes all 4 gate planes of its 16x16 tile (32 fp32 accums);
// in-register epilogue per rule; logits as 8 fixed-order partials.
// ---------------------------------------------------------------------------
__global__ void __launch_bounds__(256, 2)
kGRU(const float* __restrict__ Hin,
     const float* __restrict__ bih, const float* __restrict__ bhh) {
    extern __shared__ char smem[];
    const uint32_t sb = smem_u32(smem);
    const int tid = threadIdx.x;
    const int w = tid >> 5, lane = tid & 31;
    const int b0 = blockIdx.x * TM;
    const int n0c = blockIdx.y * 32;

    const int rg = w & 3;
    const int cg = w >> 2;

    const int rowa = rg * 16 + ((lane >> 3) & 1) * 8 + (lane & 7);
    const uint32_t aoff = (uint32_t)rowa * 64;
    const int swa = (rowa >> 1) & 3;
    const int hiA = lane >> 4;
    const int nbase = cg * 16 + ((lane >> 4) & 1) * 8 + (lane & 7);
    const uint32_t boff = (uint32_t)nbase * 64;
    const int swb = (nbase >> 1) & 3;
    const int hiB = (lane >> 3) & 1;

    float aR[2][4], aZ[2][4], aIN[2][4], aHN[2][4];
    #pragma unroll
    for (int nt = 0; nt < 2; ++nt)
        #pragma unroll
        for (int j = 0; j < 4; ++j)
            { aR[nt][j] = 0.f; aZ[nt][j] = 0.f; aIN[nt][j] = 0.f; aHN[nt][j] = 0.f; }

    // prologue: group0 = A + B(0), group1 = B(1), group2 = B(2)
    load_A_all(sb, b0, tid);
    load_B_stage(sb + B_BASE, 0, n0c, tid, 0);
    asm volatile("cp.async.commit_group;" ::: "memory");
    load_B_stage(sb + B_BASE + B_STAGE, 0, n0c, tid, 32);
    asm volatile("cp.async.commit_group;" ::: "memory");
    load_B_stage(sb + B_BASE + 2 * B_STAGE, 0, n0c, tid, 64);
    asm volatile("cp.async.commit_group;" ::: "memory");

    for (int ru = 0; ru < RULES; ++ru) {
        #pragma unroll
        for (int ch = 0; ch < 4; ++ch) {
            const int i = ru * 4 + ch;
            if (i < 62)      asm volatile("cp.async.wait_group 2;" ::: "memory");
            else if (i == 62) asm volatile("cp.async.wait_group 1;" ::: "memory");
            else              asm volatile("cp.async.wait_group 0;" ::: "memory");
            __syncthreads();

            const int sj = i % NSTG;
            const uint32_t bst = sb + B_BASE + (uint32_t)sj * B_STAGE;
            #pragma unroll
            for (int ks = 0; ks < 2; ++ks) {
                const uint32_t kxa = (uint32_t)(((ks * 2 + hiA) ^ swa) << 4);
                const uint32_t kxb = (uint32_t)(((ks * 2 + hiB) ^ swb) << 4);
                #pragma unroll
                for (int s = 0; s < 2; ++s) {
                    uint32_t ah[4], al[4];
                    const uint32_t abase = sb + ch * A_CHUNK + (uint32_t)(s * 2) * A_TILE;
                    ldsm4(ah, abase + aoff + kxa);
                    ldsm4(al, abase + A_TILE + aoff + kxa);

                    uint32_t bb[4];
                    // r gate
                    ldsm4(bb, bst + (uint32_t)(s * 3 + 0) * B_ARR + boff + kxb);
                    mma16816(aR[0], ah, bb + 0); mma16816(aR[0], al, bb + 0);
                    mma16816(aR[1], ah, bb + 2); mma16816(aR[1], al, bb + 2);
                    // z gate
                    ldsm4(bb, bst + (uint32_t)(s * 3 + 1) * B_ARR + boff + kxb);
                    mma16816(aZ[0], ah, bb + 0); mma16816(aZ[0], al, bb + 0);
                    mma16816(aZ[1], ah, bb + 2); mma16816(aZ[1], al, bb + 2);
                    // n gate -> i_n (s=0) / h_n (s=1)
                    ldsm4(bb, bst + (uint32_t)(s * 3 + 2) * B_ARR + boff + kxb);
                    float (*aN)[4] = s ? aHN : aIN;
                    mma16816(aN[0], ah, bb + 0); mma16816(aN[0], al, bb + 0);
                    mma16816(aN[1], ah, bb + 2); mma16816(aN[1], al, bb + 2);
                }
            }
            __syncthreads();                       // stage consumed
            if (i < 61) {
                const int nx = i + NSTG;
                load_B_stage(sb + B_BASE + (uint32_t)(nx % NSTG) * B_STAGE,
                             nx >> 2, n0c, tid, (nx & 3) * 32);
                asm volatile("cp.async.commit_group;" ::: "memory");
            }
        }

        // ---- in-register epilogue for rule ru
        {
            float dR0 = 0.0f, dR1 = 0.0f;
            const size_t bgA = (size_t)(b0 + rg * 16 + (lane >> 2));
            #pragma unroll
            for (int nt = 0; nt < 2; ++nt) {
                const int colg = n0c + cg * 16 + nt * 8 + (lane & 3) * 2;
                float2 b_ir = *reinterpret_cast<const float2*>(&bih[ru * 384 + colg]);
                float2 b_iz = *reinterpret_cast<const float2*>(&bih[ru * 384 + 128 + colg]);
                float2 b_in = *reinterpret_cast<const float2*>(&bih[ru * 384 + 256 + colg]);
                float2 b_hr = *reinterpret_cast<const float2*>(&bhh[ru * 384 + colg]);
                float2 b_hz = *reinterpret_cast<const float2*>(&bhh[ru * 384 + 128 + colg]);
                float2 b_hn = *reinterpret_cast<const float2*>(&bhh[ru * 384 + 256 + colg]);
                #pragma unroll
                for (int rr2 = 0; rr2 < 2; ++rr2) {
                    const size_t bg = bgA + rr2 * 8;
                    float2 hp = *reinterpret_cast<const float2*>(&Hin[bg * KDIM + colg]);
                    float2 qv = *reinterpret_cast<const float2*>(&g_q[bg * KDIM + colg]);
                    const int j = rr2 * 2;
                    float ar0 = aR[nt][j]     + b_ir.x + b_hr.x;
                    float ar1 = aR[nt][j + 1] + b_ir.y + b_hr.y;
                    float az0 = aZ[nt][j]     + b_iz.x + b_hz.x;
                    float az1 = aZ[nt][j + 1] + b_iz.y + b_hz.y;
                    float n0 = tanhf_fast(fmaf(sigf(ar0), aHN[nt][j]     + b_hn.x,
                                               aIN[nt][j]     + b_in.x));
                    float n1 = tanhf_fast(fmaf(sigf(ar1), aHN[nt][j + 1] + b_hn.y,
                                               aIN[nt][j + 1] + b_in.y));
                    float o0 = fmaf(sigf(az0), hp.x - n0, n0);
                    float o1 = fmaf(sigf(az1), hp.y - n1, n1);
                    float2 o; o.x = o0; o.y = o1;
                    *reinterpret_cast<float2*>(
                        &g_hnext[(bg * RULES + ru) * KDIM + colg]) = o;
                    float dd = qv.x * o0 + qv.y * o1;
                    if (rr2 == 0) dR0 += dd; else dR1 += dd;
                }
            }
            dR0 += __shfl_xor_sync(0xffffffffu, dR0, 1);
            dR0 += __shfl_xor_sync(0xffffffffu, dR0, 2);
            dR1 += __shfl_xor_sync(0xffffffffu, dR1, 1);
            dR1 += __shfl_xor_sync(0xffffffffu, dR1, 2);
            if ((lane & 3) == 0) {
                const int p = blockIdx.y * 2 + cg;
                g_logits8[(bgA * RULES + ru) * 8 + p] = dR0;
                g_logits8[((bgA + 8) * RULES + ru) * 8 + p] = dR1;
            }
            #pragma unroll
            for (int nt = 0; nt < 2; ++nt)
                #pragma unroll
                for (int j = 0; j < 4; ++j)
                    { aR[nt][j] = 0.f; aZ[nt][j] = 0.f; aIN[nt][j] = 0.f; aHN[nt][j] = 0.f; }
        }
    }
}

// ---------------------------------------------------------------------------
// kSelect: fast argmax + candidate mask. One warp per b.
// ---------------------------------------------------------------------------
__global__ void kSelect(const float* __restrict__ gumbel,
                        float* __restrict__ out_h, float* __restrict__ out_attn) {
    int gwarp = (blockIdx.x * blockDim.x + threadIdx.x) >> 5;
    int lane = threadIdx.x & 31;
    if (gwarp >= BTOT) return;
    const int b = gwarp;

    float sv = -__int_as_float(0x7f800000);
    if (lane < RULES) {
        const float* p = g_logits8 + (size_t)(b * RULES + lane) * 8;
        sv = (((p[0] + p[1]) + (p[2] + p[3])) + ((p[4] + p[5]) + (p[6] + p[7])))
           + gumbel[b * RULES + lane];
    }
    float bv = sv; int bi = lane;
    #pragma unroll
    for (int off = 16; off; off >>= 1) {
        float ov = __shfl_xor_sync(0xffffffffu, bv, off);
        int   oi = __shfl_xor_sync(0xffffffffu, bi, off);
        if (ov > bv || (ov == bv && oi < bi)) { bv = ov; bi = oi; }
    }
    int rbest = bi;

    unsigned cmask = __ballot_sync(0xffffffffu, lane < RULES && sv >= bv - TAU_FIX);
    if (lane == 0 && __popc(cmask) > 1)
        g_fixmask[b] = (int)cmask;          // pre-zeroed by kZero

    float4 hv = *reinterpret_cast<const float4*>(
        g_hnext + ((size_t)b * RULES + rbest) * KDIM + lane * 4);
    *reinterpret_cast<float4*>(out_h + (size_t)b * KDIM + lane * 4) = hv;
    if (out_attn && lane < RULES)
        out_attn[b * RULES + lane] = (lane == rbest) ? 1.0f : 0.0f;
}

// ---------------------------------------------------------------------------
// kFix: fp32 recompute of candidate logits for ambiguous rows. [r9-validated]
// ---------------------------------------------------------------------------
__global__ void __launch_bounds__(128, 8)
kFix(const float* __restrict__ X, const float* __restrict__ H,
     const float* __restrict__ Wih, const float* __restrict__ Whh,
     const float* __restrict__ bih, const float* __restrict__ bhh,
     const float* __restrict__ gumbel,
     float* __restrict__ out_h, float* __restrict__ out_attn) {
    const int b = blockIdx.x;
    const int mask = g_fixmask[b];
    if (mask == 0) return;

    __shared__ float xs[KDIM], hs[KDIM], qs[KDIM], red[4];
    __shared__ int s_best;
    const int t = threadIdx.x;
    xs[t] = X[(size_t)b * KDIM + t];
    hs[t] = H[(size_t)b * KDIM + t];
    qs[t] = g_q[(size_t)b * KDIM + t];
    __syncthreads();

    float bestv = -__int_as_float(0x7f800000);
    int bestr = 0;
    for (int r = 0; r < RULES; ++r) {
        if (!((mask >> r) & 1)) continue;
        const float* Wi = Wih + (size_t)r * 384 * KDIM;
        const float* Wh = Whh + (size_t)r * 384 * KDIM;
        float ir = bih[r * 384 + t],        hr = bhh[r * 384 + t];
        float iz = bih[r * 384 + 128 + t],  hz = bhh[r * 384 + 128 + t];
        float in_ = bih[r * 384 + 256 + t], hn = bhh[r * 384 + 256 + t];
        const float* wir = Wi + (size_t)t * KDIM;
        const float* wiz = Wi + (size_t)(128 + t) * KDIM;
        const float* win = Wi + (size_t)(256 + t) * KDIM;
        const float* whr = Wh + (size_t)t * KDIM;
        const float* whz = Wh + (size_t)(128 + t) * KDIM;
        const float* whn = Wh + (size_t)(256 + t) * KDIM;
        for (int k = 0; k < KDIM; ++k) {
            float xk = xs[k], hk = hs[k];
            ir = fmaf(xk, wir[k], ir);   hr = fmaf(hk, whr[k], hr);
            iz = fmaf(xk, wiz[k], iz);   hz = fmaf(hk, whz[k], hz);
            in_ = fmaf(xk, win[k], in_); hn = fmaf(hk, whn[k], hn);
        }
        float rg = sigf(ir + hr);
        float zg = sigf(iz + hz);
        float nn = tanhf_fast(fmaf(rg, hn, in_));
        float hv = fmaf(zg, hs[t] - nn, nn);
        float d = qs[t] * hv;
        #pragma unroll
        for (int off = 16; off; off >>= 1)
            d += __shfl_xor_sync(0xffffffffu, d, off);
        if ((t & 31) == 0) red[t >> 5] = d;
        __syncthreads();
        if (t == 0) {
            float logit = red[0] + red[1] + red[2] + red[3];
            float s = logit + gumbel[b * RULES + r];
            if (s > bestv) { bestv = s; bestr = r; }
        }
        __syncthreads();
    }
    if (t == 0) s_best = bestr;
    __syncthreads();
    const int rtrue = s_best;

    out_h[(size_t)b * KDIM + t] =
        g_hnext[((size_t)b * RULES + rtrue) * KDIM + t];
    if (out_attn && t < RULES)
        out_attn[b * RULES + t] = (t == rtrue) ? 1.0f : 0.0f;
}

// ---------------------------------------------------------------------------
extern "C" void kernel_launch(void* const* d_in, const int* in_sizes, int n_in,
                              void* d_out, int out_size) {
    const float* X      = (const float*)d_in[0];
    const float* H      = (const float*)d_in[1];
    const float* Wih    = (const float*)d_in[2];
    const float* Whh    = (const float*)d_in[3];
    const float* bih    = (const float*)d_in[4];
    const float* bhh    = (const float*)d_in[5];
    const float* wread  = (const float*)d_in[6];
    const float* wwrite = (const float*)d_in[7];
    const float* gum    = (const float*)d_in[8];
    float* out = (float*)d_out;

    cudaFuncSetAttribute(kGRU, cudaFuncAttributeMaxDynamicSharedMemorySize, SMEM_TOTAL);

    kPre<<<NA / 256 + 1, 256>>>(X, H, Wih, Whh, wread, wwrite);     // 1
    kQ<<<BTOT / 16, 256>>>(H);                                      // 2
    kZero<<<BTOT / 256, 256>>>();                                   // 3
    dim3 grid(BTOT / TM, 4);
    kGRU<<<grid, 256, SMEM_TOTAL>>>(H, bih, bhh);                   // 4 <- ncu slot

    const int HO = BTOT * KDIM;
    float* attn = (out_size >= HO + BTOT * RULES) ? out + HO : nullptr;
    kSelect<<<BTOT / 8, 256>>>(gum, out, attn);                     // 5
    kFix<<<BTOT, 128>>>(X, H, Wih, Whh, bih, bhh, gum, out, attn);  // 6
}

// round 17
// speedup vs baseline: 1.2815x; 1.1504x over previous
#include <cuda_runtime.h>
#include <cuda_fp16.h>
#include <cstdint>

// ---------------------------------------------------------------------------
// SharedGroupGRU: B=16384 rows, IN=HID=128, KEY=64, RULES=16.
//   att == y_hard (argmax of logits+gumbel); logits[b,r] = q[b].hnext[b,r],
//   q = H @ (w_read @ W_write).
// Round 17 = re-run of round 16 (broker/container flake #4 killed the bench
// pre-compile; code audited — atomics, replay reset, persistent loop OK).
// r15 kGRU (A-resident rule loop, TM=64, 2 CTAs/SM, 3-stage B; profiled
// 368.6us) unchanged. kFix = compacted worklist (atomicAdd append in kSelect,
// 64 persistent blocks) replacing the 16384-block early-exit sweep that
// cross-round accounting fingers for ~200us. Output deterministic: worklist
// order varies, each entry writes only its own row.
// ---------------------------------------------------------------------------

#define BTOT   16384
#define KDIM   128
#define RULES  16
#define TM     64
#define NA     (BTOT * KDIM)          // 2,097,152
#define NW     (RULES * 384 * KDIM)   // 786,432
#define WS     (RULES * 128 * KDIM)   // per-W-slab elems
#define TAU_FIX 2e-3f

typedef unsigned long long u64;

// -------------------- device scratch (static; no runtime alloc) ------------
__device__ float g_M[KDIM * KDIM];
__device__ float g_q[BTOT * KDIM];
__device__ float g_logits8[BTOT * RULES * 8];   // 8 fixed-order partials
__device__ int   g_fixmask[BTOT];
__device__ int   g_fixlist[BTOT];
__device__ int   g_nfix;
__device__ float g_hnext[(size_t)BTOT * RULES * KDIM];

// A slabs: 0=X16 1=Xl16 2=H16 3=Hl16, each [BTOT][128] fp16
__device__ __half g_Asp[4 * NA];
// W slabs: arr = s*3 + g (s:0=ih,1=hh; g:r,z,n), each [RULES][128][128] fp16
__device__ __half g_Wsp[6 * WS];

// -------------------- helpers ----------------------------------------------
__device__ __forceinline__ uint32_t smem_u32(const void* p) {
    uint32_t a;
    asm("{ .reg .u64 t; cvta.to.shared.u64 t, %1; cvt.u32.u64 %0, t; }" : "=r"(a) : "l"(p));
    return a;
}
__device__ __forceinline__ void cpasync16(uint32_t dst, const void* src) {
    asm volatile("cp.async.cg.shared.global [%0], [%1], 16;" :: "r"(dst), "l"(src));
}
__device__ __forceinline__ void ldsm4(uint32_t* r, uint32_t a) {
    asm volatile("ldmatrix.sync.aligned.m8n8.x4.shared.b16 {%0,%1,%2,%3}, [%4];"
                 : "=r"(r[0]), "=r"(r[1]), "=r"(r[2]), "=r"(r[3]) : "r"(a));
}
__device__ __forceinline__ void mma16816(float* d, const uint32_t* a, const uint32_t* b) {
    asm volatile("mma.sync.aligned.m16n8k16.row.col.f32.f16.f16.f32 "
                 "{%0,%1,%2,%3}, {%4,%5,%6,%7}, {%8,%9}, {%0,%1,%2,%3};"
                 : "+f"(d[0]), "+f"(d[1]), "+f"(d[2]), "+f"(d[3])
                 : "r"(a[0]), "r"(a[1]), "r"(a[2]), "r"(a[3]), "r"(b[0]), "r"(b[1]));
}
__device__ __forceinline__ float sigf(float x) {
    return __fdividef(1.0f, 1.0f + __expf(-x));
}
__device__ __forceinline__ float tanhf_fast(float x) {
    float e = __expf(2.0f * x);
    return 1.0f - __fdividef(2.0f, e + 1.0f);
}

// -------------------- smem geometry ----------------------------------------
// A resident: [chunk 0..3][tile 0..3] 4KB each (64 rows x 32 k, 64B rows)
#define A_TILE      4096
#define A_CHUNK     16384              // 4 tiles
#define B_BASE      65536              // after A region
#define B_ARR       2048               // 32 rows x 32 k fp16
#define B_STAGE     12288              // 6 arrs
#define NSTG        3
#define SMEM_TOTAL  (B_BASE + NSTG * B_STAGE)   // 102,400 B -> 2 CTAs/SM

// ---------------------------------------------------------------------------
// kPre: fp16 conversions + M (last block) + g_nfix reset.
// ---------------------------------------------------------------------------
__global__ void kPre(const float* __restrict__ X, const float* __restrict__ H,
                     const float* __restrict__ Wih, const float* __restrict__ Whh,
                     const float* __restrict__ wread, const float* __restrict__ wwrite) {
    if (blockIdx.x == gridDim.x - 1) {
        if (threadIdx.x == 0) g_nfix = 0;
        for (int o = threadIdx.x; o < KDIM * KDIM; o += blockDim.x) {
            int hp = o >> 7, h = o & 127;
            float s = 0.0f;
            #pragma unroll 8
            for (int k = 0; k < 64; ++k)
                s = fmaf(wread[hp * 64 + k], wwrite[k * 128 + h], s);
            g_M[o] = s;
        }
        return;
    }
    int i = blockIdx.x * blockDim.x + threadIdx.x;
    if (i < NA) {
        float v = X[i];
        __half h = __float2half_rn(v);
        g_Asp[i] = h;
        g_Asp[NA + i] = __float2half_rn(v - __half2float(h));
        v = H[i];
        h = __float2half_rn(v);
        g_Asp[2 * NA + i] = h;
        g_Asp[3 * NA + i] = __float2half_rn(v - __half2float(h));
    }
    if (i < NW) {
        int rule = i / 49152;
        int rem  = i - rule * 49152;
        int row384 = rem >> 7, k = rem & 127;
        int g = row384 >> 7, rowg = row384 & 127;
        size_t dst = ((size_t)rule * 128 + rowg) * 128 + k;
        g_Wsp[(size_t)g * WS + dst]       = __float2half_rn(Wih[i]);
        g_Wsp[(size_t)(3 + g) * WS + dst] = __float2half_rn(Whh[i]);
    }
}

// ---------------------------------------------------------------------------
// kQ: g_q = H @ g_M (fp32; feeds argmax path)
// ---------------------------------------------------------------------------
__global__ void kQ(const float* __restrict__ Hin) {
    __shared__ float Hs[16][KDIM];
    int b0 = blockIdx.x * 16;
    for (int i = threadIdx.x; i < 16 * KDIM; i += blockDim.x)
        Hs[i >> 7][i & 127] = Hin[b0 * KDIM + i];
    __syncthreads();

    int h  = threadIdx.x & 127;
    int rr = threadIdx.x >> 7;
    float acc[8];
    #pragma unroll
    for (int j = 0; j < 8; ++j) acc[j] = 0.0f;
    for (int k = 0; k < KDIM; ++k) {
        float m = g_M[k * KDIM + h];
        #pragma unroll
        for (int j = 0; j < 8; ++j)
            acc[j] = fmaf(Hs[rr + 2 * j][k], m, acc[j]);
    }
    #pragma unroll
    for (int j = 0; j < 8; ++j)
        g_q[(size_t)(b0 + rr + 2 * j) * KDIM + h] = acc[j];
}

// ---------------------------------------------------------------------------
// kZero: clears fixmask (belt-and-braces) + keeps kGRU in the profiled slot.
// ---------------------------------------------------------------------------
__global__ void kZero() {
    int i = blockIdx.x * blockDim.x + threadIdx.x;
    if (i < BTOT) g_fixmask[i] = 0;
}

// ---------------------------------------------------------------------------
// kGRU loaders (256 threads)
// ---------------------------------------------------------------------------
__device__ __forceinline__ void load_A_all(uint32_t sb, int b0, int tid) {
    #pragma unroll
    for (int it = 0; it < 16; ++it) {
        int idx  = it * 256 + tid;
        int ch   = idx >> 10;
        int tile = (idx >> 8) & 3;
        int row  = (idx >> 2) & 63;
        int cc   = idx & 3;
        uint32_t sw = (uint32_t)((cc ^ ((row >> 1) & 3)) << 4);
        const __half* src =
            g_Asp + (size_t)tile * NA + (size_t)(b0 + row) * KDIM + ch * 32 + cc * 8;
        cpasync16(sb + ch * A_CHUNK + tile * A_TILE + row * 64 + sw, src);
    }
}
__device__ __forceinline__ void load_B_stage(uint32_t bst, int rule, int n0c,
                                             int tid, int k0) {
    #pragma unroll
    for (int a = 0; a < 3; ++a) {
        int idx = a * 256 + tid;
        int arr = idx >> 7;
        int row = (idx >> 2) & 31;
        int cc  = idx & 3;
        uint32_t sw = (uint32_t)((cc ^ ((row >> 1) & 3)) << 4);
        const __half* src =
            g_Wsp + (size_t)arr * WS + ((size_t)rule * 128 + n0c + row) * KDIM + k0 + cc * 8;
        cpasync16(bst + arr * B_ARR + row * 64 + sw, src);
    }
}

// ---------------------------------------------------------------------------
// kGRU: grid (256, 4), block 256 = 8 warps, 2 CTAs/SM. Rule loop, 3-stage B.
// [unchanged from r15: profiled 368.6us, tensor 52.7%, L1 67.4%]
// ---------------------------------------------------------------------------
__global__ void __launch_bounds__(256, 2)
kGRU(const float* __restrict__ Hin,
     const float* __restrict__ bih, const float* __restrict__ bhh) {
    extern __shared__ char smem[];
    const uint32_t sb = smem_u32(smem);
    const int tid = threadIdx.x;
    const int w = tid >> 5, lane = tid & 31;
    const int b0 = blockIdx.x * TM;
    const int n0c = blockIdx.y * 32;

    const int rg = w & 3;
    const int cg = w >> 2;

    const int rowa = rg * 16 + ((lane >> 3) & 1) * 8 + (lane & 7);
    const uint32_t aoff = (uint32_t)rowa * 64;
    const int swa = (rowa >> 1) & 3;
    const int hiA = lane >> 4;
    const int nbase = cg * 16 + ((lane >> 4) & 1) * 8 + (lane & 7);
    const uint32_t boff = (uint32_t)nbase * 64;
    const int swb = (nbase >> 1) & 3;
    const int hiB = (lane >> 3) & 1;

    float aR[2][4], aZ[2][4], aIN[2][4], aHN[2][4];
    #pragma unroll
    for (int nt = 0; nt < 2; ++nt)
        #pragma unroll
        for (int j = 0; j < 4; ++j)
            { aR[nt][j] = 0.f; aZ[nt][j] = 0.f; aIN[nt][j] = 0.f; aHN[nt][j] = 0.f; }

    load_A_all(sb, b0, tid);
    load_B_stage(sb + B_BASE, 0, n0c, tid, 0);
    asm volatile("cp.async.commit_group;" ::: "memory");
    load_B_stage(sb + B_BASE + B_STAGE, 0, n0c, tid, 32);
    asm volatile("cp.async.commit_group;" ::: "memory");
    load_B_stage(sb + B_BASE + 2 * B_STAGE, 0, n0c, tid, 64);
    asm volatile("cp.async.commit_group;" ::: "memory");

    for (int ru = 0; ru < RULES; ++ru) {
        #pragma unroll
        for (int ch = 0; ch < 4; ++ch) {
            const int i = ru * 4 + ch;
            if (i < 62)       asm volatile("cp.async.wait_group 2;" ::: "memory");
            else if (i == 62) asm volatile("cp.async.wait_group 1;" ::: "memory");
            else              asm volatile("cp.async.wait_group 0;" ::: "memory");
            __syncthreads();

            const int sj = i % NSTG;
            const uint32_t bst = sb + B_BASE + (uint32_t)sj * B_STAGE;
            #pragma unroll
            for (int ks = 0; ks < 2; ++ks) {
                const uint32_t kxa = (uint32_t)(((ks * 2 + hiA) ^ swa) << 4);
                const uint32_t kxb = (uint32_t)(((ks * 2 + hiB) ^ swb) << 4);
                #pragma unroll
                for (int s = 0; s < 2; ++s) {
                    uint32_t ah[4], al[4];
                    const uint32_t abase = sb + ch * A_CHUNK + (uint32_t)(s * 2) * A_TILE;
                    ldsm4(ah, abase + aoff + kxa);
                    ldsm4(al, abase + A_TILE + aoff + kxa);

                    uint32_t bb[4];
                    ldsm4(bb, bst + (uint32_t)(s * 3 + 0) * B_ARR + boff + kxb);
                    mma16816(aR[0], ah, bb + 0); mma16816(aR[0], al, bb + 0);
                    mma16816(aR[1], ah, bb + 2); mma16816(aR[1], al, bb + 2);
                    ldsm4(bb, bst + (uint32_t)(s * 3 + 1) * B_ARR + boff + kxb);
                    mma16816(aZ[0], ah, bb + 0); mma16816(aZ[0], al, bb + 0);
                    mma16816(aZ[1], ah, bb + 2); mma16816(aZ[1], al, bb + 2);
                    ldsm4(bb, bst + (uint32_t)(s * 3 + 2) * B_ARR + boff + kxb);
                    float (*aN)[4] = s ? aHN : aIN;
                    mma16816(aN[0], ah, bb + 0); mma16816(aN[0], al, bb + 0);
                    mma16816(aN[1], ah, bb + 2); mma16816(aN[1], al, bb + 2);
                }
            }
            __syncthreads();
            if (i < 61) {
                const int nx = i + NSTG;
                load_B_stage(sb + B_BASE + (uint32_t)(nx % NSTG) * B_STAGE,
                             nx >> 2, n0c, tid, (nx & 3) * 32);
                asm volatile("cp.async.commit_group;" ::: "memory");
            }
        }

        // ---- in-register epilogue for rule ru
        {
            float dR0 = 0.0f, dR1 = 0.0f;
            const size_t bgA = (size_t)(b0 + rg * 16 + (lane >> 2));
            #pragma unroll
            for (int nt = 0; nt < 2; ++nt) {
                const int colg = n0c + cg * 16 + nt * 8 + (lane & 3) * 2;
                float2 b_ir = *reinterpret_cast<const float2*>(&bih[ru * 384 + colg]);
                float2 b_iz = *reinterpret_cast<const float2*>(&bih[ru * 384 + 128 + colg]);
                float2 b_in = *reinterpret_cast<const float2*>(&bih[ru * 384 + 256 + colg]);
                float2 b_hr = *reinterpret_cast<const float2*>(&bhh[ru * 384 + colg]);
                float2 b_hz = *reinterpret_cast<const float2*>(&bhh[ru * 384 + 128 + colg]);
                float2 b_hn = *reinterpret_cast<const float2*>(&bhh[ru * 384 + 256 + colg]);
                #pragma unroll
                for (int rr2 = 0; rr2 < 2; ++rr2) {
                    const size_t bg = bgA + rr2 * 8;
                    float2 hp = *reinterpret_cast<const float2*>(&Hin[bg * KDIM + colg]);
                    float2 qv = *reinterpret_cast<const float2*>(&g_q[bg * KDIM + colg]);
                    const int j = rr2 * 2;
                    float ar0 = aR[nt][j]     + b_ir.x + b_hr.x;
                    float ar1 = aR[nt][j + 1] + b_ir.y + b_hr.y;
                    float az0 = aZ[nt][j]     + b_iz.x + b_hz.x;
                    float az1 = aZ[nt][j + 1] + b_iz.y + b_hz.y;
                    float n0 = tanhf_fast(fmaf(sigf(ar0), aHN[nt][j]     + b_hn.x,
                                               aIN[nt][j]     + b_in.x));
                    float n1 = tanhf_fast(fmaf(sigf(ar1), aHN[nt][j + 1] + b_hn.y,
                                               aIN[nt][j + 1] + b_in.y));
                    float o0 = fmaf(sigf(az0), hp.x - n0, n0);
                    float o1 = fmaf(sigf(az1), hp.y - n1, n1);
                    float2 o; o.x = o0; o.y = o1;
                    *reinterpret_cast<float2*>(
                        &g_hnext[(bg * RULES + ru) * KDIM + colg]) = o;
                    float dd = qv.x * o0 + qv.y * o1;
                    if (rr2 == 0) dR0 += dd; else dR1 += dd;
                }
            }
            dR0 += __shfl_xor_sync(0xffffffffu, dR0, 1);
            dR0 += __shfl_xor_sync(0xffffffffu, dR0, 2);
            dR1 += __shfl_xor_sync(0xffffffffu, dR1, 1);
            dR1 += __shfl_xor_sync(0xffffffffu, dR1, 2);
            if ((lane & 3) == 0) {
                const int p = blockIdx.y * 2 + cg;
                g_logits8[(bgA * RULES + ru) * 8 + p] = dR0;
                g_logits8[((bgA + 8) * RULES + ru) * 8 + p] = dR1;
            }
            #pragma unroll
            for (int nt = 0; nt < 2; ++nt)
                #pragma unroll
                for (int j = 0; j < 4; ++j)
                    { aR[nt][j] = 0.f; aZ[nt][j] = 0.f; aIN[nt][j] = 0.f; aHN[nt][j] = 0.f; }
        }
    }
}

// ---------------------------------------------------------------------------
// kSelect: fast argmax + worklist append for ambiguous rows. One warp per b.
// ---------------------------------------------------------------------------
__global__ void kSelect(const float* __restrict__ gumbel,
                        float* __restrict__ out_h, float* __restrict__ out_attn) {
    int gwarp = (blockIdx.x * blockDim.x + threadIdx.x) >> 5;
    int lane = threadIdx.x & 31;
    if (gwarp >= BTOT) return;
    const int b = gwarp;

    float sv = -__int_as_float(0x7f800000);
    if (lane < RULES) {
        const float* p = g_logits8 + (size_t)(b * RULES + lane) * 8;
        sv = (((p[0] + p[1]) + (p[2] + p[3])) + ((p[4] + p[5]) + (p[6] + p[7])))
           + gumbel[b * RULES + lane];
    }
    float bv = sv; int bi = lane;
    #pragma unroll
    for (int off = 16; off; off >>= 1) {
        float ov = __shfl_xor_sync(0xffffffffu, bv, off);
        int   oi = __shfl_xor_sync(0xffffffffu, bi, off);
        if (ov > bv || (ov == bv && oi < bi)) { bv = ov; bi = oi; }
    }
    int rbest = bi;

    unsigned cmask = __ballot_sync(0xffffffffu, lane < RULES && sv >= bv - TAU_FIX);
    if (lane == 0 && __popc(cmask) > 1) {
        int slot = atomicAdd(&g_nfix, 1);
        g_fixlist[slot] = b;
        g_fixmask[b] = (int)cmask;
    }

    float4 hv = *reinterpret_cast<const float4*>(
        g_hnext + ((size_t)b * RULES + rbest) * KDIM + lane * 4);
    *reinterpret_cast<float4*>(out_h + (size_t)b * KDIM + lane * 4) = hv;
    if (out_attn && lane < RULES)
        out_attn[b * RULES + lane] = (lane == rbest) ? 1.0f : 0.0f;
}

// ---------------------------------------------------------------------------
// kFix: worklist-driven fp32 recompute for ambiguous rows. 64 persistent
// blocks stride g_fixlist[0..g_nfix). Per-row body unchanged (r9-validated).
// ---------------------------------------------------------------------------
__global__ void __launch_bounds__(128, 8)
kFix(const float* __restrict__ X, const float* __restrict__ H,
     const float* __restrict__ Wih, const float* __restrict__ Whh,
     const float* __restrict__ bih, const float* __restrict__ bhh,
     const float* __restrict__ gumbel,
     float* __restrict__ out_h, float* __restrict__ out_attn) {
    __shared__ float xs[KDIM], hs[KDIM], qs[KDIM], red[4];
    __shared__ int s_best;
    const int t = threadIdx.x;
    const int nfix = g_nfix;

    for (int idx = blockIdx.x; idx < nfix; idx += gridDim.x) {
        const int b = g_fixlist[idx];
        const int mask = g_fixmask[b];

        xs[t] = X[(size_t)b * KDIM + t];
        hs[t] = H[(size_t)b * KDIM + t];
        qs[t] = g_q[(size_t)b * KDIM + t];
        __syncthreads();

        float bestv = -__int_as_float(0x7f800000);
        int bestr = 0;
        for (int r = 0; r < RULES; ++r) {
            if (!((mask >> r) & 1)) continue;
            const float* Wi = Wih + (size_t)r * 384 * KDIM;
            const float* Wh = Whh + (size_t)r * 384 * KDIM;
            float ir = bih[r * 384 + t],        hr = bhh[r * 384 + t];
            float iz = bih[r * 384 + 128 + t],  hz = bhh[r * 384 + 128 + t];
            float in_ = bih[r * 384 + 256 + t], hn = bhh[r * 384 + 256 + t];
            const float* wir = Wi + (size_t)t * KDIM;
            const float* wiz = Wi + (size_t)(128 + t) * KDIM;
            const float* win = Wi + (size_t)(256 + t) * KDIM;
            const float* whr = Wh + (size_t)t * KDIM;
            const float* whz = Wh + (size_t)(128 + t) * KDIM;
            const float* whn = Wh + (size_t)(256 + t) * KDIM;
            for (int k = 0; k < KDIM; ++k) {
                float xk = xs[k], hk = hs[k];
                ir = fmaf(xk, wir[k], ir);   hr = fmaf(hk, whr[k], hr);
                iz = fmaf(xk, wiz[k], iz);   hz = fmaf(hk, whz[k], hz);
                in_ = fmaf(xk, win[k], in_); hn = fmaf(hk, whn[k], hn);
            }
            float rg = sigf(ir + hr);
            float zg = sigf(iz + hz);
            float nn = tanhf_fast(fmaf(rg, hn, in_));
            float hv = fmaf(zg, hs[t] - nn, nn);
            float d = qs[t] * hv;
            #pragma unroll
            for (int off = 16; off; off >>= 1)
                d += __shfl_xor_sync(0xffffffffu, d, off);
            if ((t & 31) == 0) red[t >> 5] = d;
            __syncthreads();
            if (t == 0) {
                float logit = red[0] + red[1] + red[2] + red[3];
                float s = logit + gumbel[b * RULES + r];
                if (s > bestv) { bestv = s; bestr = r; }
            }
            __syncthreads();
        }
        if (t == 0) s_best = bestr;
        __syncthreads();
        const int rtrue = s_best;

        out_h[(size_t)b * KDIM + t] =
            g_hnext[((size_t)b * RULES + rtrue) * KDIM + t];
        if (out_attn && t < RULES)
            out_attn[b * RULES + t] = (t == rtrue) ? 1.0f : 0.0f;
        __syncthreads();
    }
}

// ---------------------------------------------------------------------------
extern "C" void kernel_launch(void* const* d_in, const int* in_sizes, int n_in,
                              void* d_out, int out_size) {
    const float* X      = (const float*)d_in[0];
    const float* H      = (const float*)d_in[1];
    const float* Wih    = (const float*)d_in[2];
    const float* Whh    = (const float*)d_in[3];
    const float* bih    = (const float*)d_in[4];
    const float* bhh    = (const float*)d_in[5];
    const float* wread  = (const float*)d_in[6];
    const float* wwrite = (const float*)d_in[7];
    const float* gum    = (const float*)d_in[8];
    float* out = (float*)d_out;

    cudaFuncSetAttribute(kGRU, cudaFuncAttributeMaxDynamicSharedMemorySize, SMEM_TOTAL);

    kPre<<<NA / 256 + 1, 256>>>(X, H, Wih, Whh, wread, wwrite);     // 1 (zeroes g_nfix)
    kQ<<<BTOT / 16, 256>>>(H);                                      // 2
    kZero<<<BTOT / 256, 256>>>();                                   // 3
    dim3 grid(BTOT / TM, 4);
    kGRU<<<grid, 256, SMEM_TOTAL>>>(H, bih, bhh);                   // 4 <- ncu slot

    const int HO = BTOT * KDIM;
    float* attn = (out_size >= HO + BTOT * RULES) ? out + HO : nullptr;
    kSelect<<<BTOT / 8, 256>>>(gum, out, attn);                     // 5
    kFix<<<64, 128>>>(X, H, Wih, Whh, bih, bhh, gum, out, attn);    // 6
}